// round 15
// baseline (speedup 1.0000x reference)
#include <cuda_runtime.h>
#include <cstdint>

#define BB 2
#define SS 5
#define CC 256
#define HH 192
#define WW 192
#define KK 7
#define NH 28
#define NW 28
#define HID 16

__device__ float g_buf[BB * SS * CC * NH * NW];       // 8.03 MB
__device__ float logits_buf[BB * SS * NH * NW];       // 31.4 KB

__device__ __forceinline__ uint32_t smem_u32(const void* p) {
    uint32_t a;
    asm("{ .reg .u64 t; cvta.to.shared.u64 t, %1; cvt.u32.u64 %0, t; }"
        : "=r"(a) : "l"(p));
    return a;
}

// ---------------------------------------------------------------------------
// Kernel 1: 7x7 window means, DMA-fed pipeline, DEPTH-3 buffers.
// Block = half of one (bs,c) image = 14 strips, 7 stages of 2 strips, each
// stage one contiguous 10.75KB cp.async.bulk. Depth-3 gives each buffer a
// full extra stage of slack so consume-phase jitter never bubbles the DMA
// stream. smem ~35.4KB -> 6 blocks/SM, ~190KB DMA in flight per SM.
// ---------------------------------------------------------------------------
#define MT     192
#define MROWS  14
#define MSF    (MROWS * WW)
#define MDEPTH 3

__global__ __launch_bounds__(MT) void k_means(const float* __restrict__ x) {
    const int c  = blockIdx.x;
    const int bs = blockIdx.y;          // b*SS + s
    const int z  = blockIdx.z;          // image half
    const int t  = threadIdx.x;

    __shared__ float buf[MDEPTH][MSF];                   // 32256 B
    __shared__ float scol[2][2][WW];                     //  3072 B
    __shared__ __align__(8) unsigned long long mbar[MDEPTH];

    const float* img = x + (size_t)(bs * CC + c) * HH * WW;
    const int strip0 = z * 14;

    auto stage_rows = [&](int s) -> int {
        int rv = HH - (strip0 + s * 2) * KK;
        return rv > MROWS ? MROWS : rv;
    };
    auto issue = [&](int s) {
        const int p = s % MDEPTH;
        const uint32_t bytes = (uint32_t)stage_rows(s) * WW * 4;
        const float* src = img + (size_t)(strip0 + s * 2) * KK * WW;
        const uint32_t mb  = smem_u32(&mbar[p]);
        const uint32_t dst = smem_u32(&buf[p][0]);
        asm volatile("mbarrier.arrive.expect_tx.shared.b64 _, [%0], %1;"
                     :: "r"(mb), "r"(bytes) : "memory");
        asm volatile(
            "cp.async.bulk.shared::cta.global.mbarrier::complete_tx::bytes "
            "[%0], [%1], %2, [%3];"
            :: "r"(dst), "l"(src), "r"(bytes), "r"(mb) : "memory");
    };

    if (t == 0) {
        #pragma unroll
        for (int p = 0; p < MDEPTH; p++) {
            const uint32_t mb = smem_u32(&mbar[p]);
            asm volatile("mbarrier.init.shared.b64 [%0], %1;" :: "r"(mb), "r"(1u));
        }
        asm volatile("fence.proxy.async.shared::cta;" ::: "memory");
        issue(0); issue(1); issue(2);
    }
    __syncthreads();

    for (int s = 0; s < 7; s++) {
        const int p = s % MDEPTH;
        const uint32_t ph = (s / MDEPTH) & 1;
        const uint32_t mb = smem_u32(&mbar[p]);
        asm volatile(
            "{\n\t.reg .pred P;\n\t"
            "WL_%=:\n\t"
            "mbarrier.try_wait.parity.shared.b64 P, [%0], %1;\n\t"
            "@P bra.uni WD_%=;\n\t"
            "bra.uni WL_%=;\n\t"
            "WD_%=:\n\t}"
            :: "r"(mb), "r"(ph) : "memory");

        const int rv = stage_rows(s);
        #pragma unroll
        for (int g = 0; g < 2; g++) {
            float sum = 0.f;
            #pragma unroll
            for (int r = 0; r < KK; r++) {
                const int row = g * KK + r;
                if (row < rv) sum += buf[p][row * WW + t];
            }
            scol[s & 1][g][t] = sum;
        }
        __syncthreads();
        if (t == 0 && s + MDEPTH < 7) issue(s + MDEPTH);

        if (t < 2 * NW) {
            const int g = t / NW, nw = t % NW;
            float ws = 0.f;
            #pragma unroll
            for (int i = 0; i < KK; i++) {
                const int w = nw * KK + i;
                if (w < WW) ws += scol[s & 1][g][w];
            }
            g_buf[((size_t)(bs * CC + c) * NH + (strip0 + s * 2 + g)) * NW + nw]
                = ws * (1.0f / (KK * KK));
        }
    }
}

// ---------------------------------------------------------------------------
// Kernel 2: tiny MLP over C -> logits (unchanged, validated)
// ---------------------------------------------------------------------------
__global__ void k_mlp(const float* __restrict__ w1, const float* __restrict__ b1,
                      const float* __restrict__ w2, const float* __restrict__ b2,
                      const float* __restrict__ stat) {
    const int nh = blockIdx.x;
    const int s  = blockIdx.y;
    const int b  = blockIdx.z;
    const int tid = threadIdx.x;

    __shared__ float sg[CC * NW];
    __shared__ float sw1[HID * CC];
    __shared__ float sh[NW * HID];

    const size_t gbase = (size_t)(b * SS + s) * CC * NH * NW + (size_t)nh * NW;
    for (int i = tid; i < CC * NW; i += blockDim.x) {
        int c = i / NW, nw = i % NW;
        sg[i] = g_buf[gbase + (size_t)c * NH * NW + nw];
    }
    for (int i = tid; i < HID * CC; i += blockDim.x) sw1[i] = w1[i];
    __syncthreads();

    {
        const int nw = tid % NW;
        const int j  = tid / NW;
        float acc = b1[j];
        #pragma unroll 8
        for (int c = 0; c < CC; c++)
            acc = fmaf(sg[c * NW + nw], sw1[j * CC + c], acc);
        sh[nw * HID + j] = fmaxf(acc, 0.f);
    }
    __syncthreads();

    if (tid < NW) {
        float lg = b2[0] + stat[s];
        #pragma unroll
        for (int j = 0; j < HID; j++) lg = fmaf(sh[tid * HID + j], w2[j], lg);
        logits_buf[((size_t)(b * SS + s) * NH + nh) * NW + tid] = lg;
    }
}

// ---------------------------------------------------------------------------
// Kernel 3: TMA double-buffered fuse, CPB=8, streaming stores (exact R14
// form — validated best at 139.6us).
// ---------------------------------------------------------------------------
#define CPB 8
#define FT  256
#define CH_FLOATS (SS * KK * WW)

__global__ __launch_bounds__(FT) void k_fuse(const float* __restrict__ x,
                                             float* __restrict__ out) {
    const int nh = blockIdx.x;
    const int cb = blockIdx.y;
    const int b  = blockIdx.z;
    const int t  = threadIdx.x;

    extern __shared__ float smem[];
    float* buf = smem;                    // [2][CH_FLOATS]
    float* swt = smem + 2 * CH_FLOATS;    // [SS*NW]
    __shared__ __align__(8) unsigned long long fullbar[2];

    const uint32_t bar0 = smem_u32(&fullbar[0]);
    const uint32_t bar1 = smem_u32(&fullbar[1]);
    const uint32_t bufa = smem_u32(buf);

    const int h0    = nh * KK;
    const int vrows = (HH - h0 < KK) ? (HH - h0) : KK;
    const uint32_t slice_bytes = (uint32_t)vrows * WW * 4;

    if (t == 0) {
        asm volatile("mbarrier.init.shared.b64 [%0], %1;" :: "r"(bar0), "r"(1u));
        asm volatile("mbarrier.init.shared.b64 [%0], %1;" :: "r"(bar1), "r"(1u));
        asm volatile("fence.proxy.async.shared::cta;" ::: "memory");
    }
    if (vrows < KK) {
        const int padrows = KK - vrows;
        const int total = 2 * SS * padrows * WW;
        for (int i = t; i < total; i += FT) {
            const int w  = i % WW;
            const int r  = i / WW;
            const int pr = r % padrows;
            const int ps = r / padrows;
            buf[ps * KK * WW + (vrows + pr) * WW + w] = 0.f;
        }
    }

    auto issue = [&](int ch) {
        const int c = cb * CPB + ch;
        const int p = ch & 1;
        const uint32_t mbar = p ? bar1 : bar0;
        asm volatile("mbarrier.arrive.expect_tx.shared.b64 _, [%0], %1;"
                     :: "r"(mbar), "r"(slice_bytes * SS) : "memory");
        #pragma unroll
        for (int s = 0; s < SS; s++) {
            const float* src = x + ((size_t)((b * SS + s) * CC + c) * HH + h0) * WW;
            const uint32_t dst = bufa + (uint32_t)(p * CH_FLOATS + s * KK * WW) * 4;
            asm volatile(
                "cp.async.bulk.shared::cta.global.mbarrier::complete_tx::bytes "
                "[%0], [%1], %2, [%3];"
                :: "r"(dst), "l"(src), "r"(slice_bytes), "r"(mbar) : "memory");
        }
    };

    if (t == 0) { issue(0); issue(1); }

    if (t < NW) {
        float lg[SS];
        float mx = -1e30f;
        #pragma unroll
        for (int s = 0; s < SS; s++) {
            lg[s] = logits_buf[((size_t)(b * SS + s) * NH + nh) * NW + t];
            mx = fmaxf(mx, lg[s]);
        }
        float sum = 0.f;
        #pragma unroll
        for (int s = 0; s < SS; s++) { lg[s] = expf(lg[s] - mx); sum += lg[s]; }
        const float inv = 1.f / sum;
        #pragma unroll
        for (int s = 0; s < SS; s++) swt[s * NW + t] = lg[s] * inv;
    }
    __syncthreads();

    const int kw   = t / NW;
    const int nw   = t % NW;
    const int wsrc = nw * KK + kw;
    const bool valid = (t < WW) && (wsrc < WW);
    float wts[SS];
    #pragma unroll
    for (int s = 0; s < SS; s++) wts[s] = swt[s * NW + (t % NW)];

    for (int ch = 0; ch < CPB; ch++) {
        const int p  = ch & 1;
        const uint32_t mbar = p ? bar1 : bar0;
        const uint32_t ph = (ch >> 1) & 1;

        asm volatile(
            "{\n\t.reg .pred P;\n\t"
            "WL_%=:\n\t"
            "mbarrier.try_wait.parity.shared.b64 P, [%0], %1;\n\t"
            "@P bra.uni WD_%=;\n\t"
            "bra.uni WL_%=;\n\t"
            "WD_%=:\n\t}"
            :: "r"(mbar), "r"(ph) : "memory");

        if (t < WW) {
            const float* smc = buf + p * CH_FLOATS;
            const int c = cb * CPB + ch;
            float* obase = out + (size_t)(b * CC + c) * HH * WW;
            #pragma unroll
            for (int kh = 0; kh < KK; kh++) {
                const int y = kh * NH + nh;
                if (y < HH) {
                    float vv = 0.f;
                    if (valid) {
                        #pragma unroll
                        for (int s = 0; s < SS; s++)
                            vv = fmaf(wts[s], smc[(s * KK + kh) * WW + wsrc], vv);
                    }
                    __stcs(&obase[(size_t)y * WW + t], vv);   // streaming store
                }
            }
        }
        __syncthreads();
        if (t == 0 && ch + 2 < CPB) issue(ch + 2);
    }
}

// ---------------------------------------------------------------------------
extern "C" void kernel_launch(void* const* d_in, const int* in_sizes, int n_in,
                              void* d_out, int out_size) {
    const float* x    = (const float*)d_in[0];
    const float* w1   = (const float*)d_in[1];
    const float* b1   = (const float*)d_in[2];
    const float* w2   = (const float*)d_in[3];
    const float* b2   = (const float*)d_in[4];
    const float* stat = (const float*)d_in[5];
    float* out = (float*)d_out;

    const int fuse_smem = (2 * CH_FLOATS + SS * NW) * sizeof(float);  // 54320 B
    cudaFuncSetAttribute(k_fuse, cudaFuncAttributeMaxDynamicSharedMemorySize, fuse_smem);

    k_means<<<dim3(CC, BB * SS, 2), MT>>>(x);
    k_mlp  <<<dim3(NH, SS, BB), NW * HID>>>(w1, b1, w2, b2, stat);
    k_fuse <<<dim3(NH, CC / CPB, BB), FT, fuse_smem>>>(x, out);
}

// round 16
// speedup vs baseline: 1.0119x; 1.0119x over previous
#include <cuda_runtime.h>
#include <cstdint>

#define BB 2
#define SS 5
#define CC 256
#define HH 192
#define WW 192
#define KK 7
#define NH 28
#define NW 28
#define HID 16

__device__ float g_buf[BB * SS * CC * NH * NW];       // 8.03 MB
__device__ float logits_buf[BB * SS * NH * NW];       // 31.4 KB

__device__ __forceinline__ uint32_t smem_u32(const void* p) {
    uint32_t a;
    asm("{ .reg .u64 t; cvta.to.shared.u64 t, %1; cvt.u32.u64 %0, t; }"
        : "=r"(a) : "l"(p));
    return a;
}

// ---------------------------------------------------------------------------
// Kernel 1: 7x7 window means, DMA-fed depth-2 pipeline (validated optimum:
// 60.2us, 81-82% DRAM). Block = half of one (bs,c) image = 14 strips,
// 7 stages of 2 strips; each stage's 14 rows are contiguous in gmem -> one
// 10.75KB cp.async.bulk into depth-2 buffers. 9 blocks/SM.
// ---------------------------------------------------------------------------
#define MT     192
#define MROWS  14
#define MSF    (MROWS * WW)

__global__ __launch_bounds__(MT) void k_means(const float* __restrict__ x) {
    const int c  = blockIdx.x;
    const int bs = blockIdx.y;          // b*SS + s
    const int z  = blockIdx.z;          // image half
    const int t  = threadIdx.x;

    __shared__ float buf[2][MSF];                        // 21504 B
    __shared__ float scol[2][2][WW];                     //  3072 B
    __shared__ __align__(8) unsigned long long mbar[2];

    const float* img = x + (size_t)(bs * CC + c) * HH * WW;
    const int strip0 = z * 14;

    auto stage_rows = [&](int s) -> int {
        int rv = HH - (strip0 + s * 2) * KK;
        return rv > MROWS ? MROWS : rv;
    };
    auto issue = [&](int s) {
        const int p = s & 1;
        const uint32_t bytes = (uint32_t)stage_rows(s) * WW * 4;
        const float* src = img + (size_t)(strip0 + s * 2) * KK * WW;
        const uint32_t mb  = smem_u32(&mbar[p]);
        const uint32_t dst = smem_u32(&buf[p][0]);
        asm volatile("mbarrier.arrive.expect_tx.shared.b64 _, [%0], %1;"
                     :: "r"(mb), "r"(bytes) : "memory");
        asm volatile(
            "cp.async.bulk.shared::cta.global.mbarrier::complete_tx::bytes "
            "[%0], [%1], %2, [%3];"
            :: "r"(dst), "l"(src), "r"(bytes), "r"(mb) : "memory");
    };

    if (t == 0) {
        const uint32_t mb0 = smem_u32(&mbar[0]), mb1 = smem_u32(&mbar[1]);
        asm volatile("mbarrier.init.shared.b64 [%0], %1;" :: "r"(mb0), "r"(1u));
        asm volatile("mbarrier.init.shared.b64 [%0], %1;" :: "r"(mb1), "r"(1u));
        asm volatile("fence.proxy.async.shared::cta;" ::: "memory");
        issue(0); issue(1);
    }
    __syncthreads();

    for (int s = 0; s < 7; s++) {
        const int p = s & 1;
        const uint32_t ph = (s >> 1) & 1;
        const uint32_t mb = smem_u32(&mbar[p]);
        asm volatile(
            "{\n\t.reg .pred P;\n\t"
            "WL_%=:\n\t"
            "mbarrier.try_wait.parity.shared.b64 P, [%0], %1;\n\t"
            "@P bra.uni WD_%=;\n\t"
            "bra.uni WL_%=;\n\t"
            "WD_%=:\n\t}"
            :: "r"(mb), "r"(ph) : "memory");

        const int rv = stage_rows(s);
        #pragma unroll
        for (int g = 0; g < 2; g++) {
            float sum = 0.f;
            #pragma unroll
            for (int r = 0; r < KK; r++) {
                const int row = g * KK + r;
                if (row < rv) sum += buf[p][row * WW + t];
            }
            scol[s & 1][g][t] = sum;
        }
        __syncthreads();
        if (t == 0 && s + 2 < 7) issue(s + 2);

        if (t < 2 * NW) {
            const int g = t / NW, nw = t % NW;
            float ws = 0.f;
            #pragma unroll
            for (int i = 0; i < KK; i++) {
                const int w = nw * KK + i;
                if (w < WW) ws += scol[s & 1][g][w];
            }
            g_buf[((size_t)(bs * CC + c) * NH + (strip0 + s * 2 + g)) * NW + nw]
                = ws * (1.0f / (KK * KK));
        }
    }
}

// ---------------------------------------------------------------------------
// Kernel 2: tiny MLP over C -> logits (unchanged, validated)
// ---------------------------------------------------------------------------
__global__ void k_mlp(const float* __restrict__ w1, const float* __restrict__ b1,
                      const float* __restrict__ w2, const float* __restrict__ b2,
                      const float* __restrict__ stat) {
    const int nh = blockIdx.x;
    const int s  = blockIdx.y;
    const int b  = blockIdx.z;
    const int tid = threadIdx.x;

    __shared__ float sg[CC * NW];
    __shared__ float sw1[HID * CC];
    __shared__ float sh[NW * HID];

    const size_t gbase = (size_t)(b * SS + s) * CC * NH * NW + (size_t)nh * NW;
    for (int i = tid; i < CC * NW; i += blockDim.x) {
        int c = i / NW, nw = i % NW;
        sg[i] = g_buf[gbase + (size_t)c * NH * NW + nw];
    }
    for (int i = tid; i < HID * CC; i += blockDim.x) sw1[i] = w1[i];
    __syncthreads();

    {
        const int nw = tid % NW;
        const int j  = tid / NW;
        float acc = b1[j];
        #pragma unroll 8
        for (int c = 0; c < CC; c++)
            acc = fmaf(sg[c * NW + nw], sw1[j * CC + c], acc);
        sh[nw * HID + j] = fmaxf(acc, 0.f);
    }
    __syncthreads();

    if (tid < NW) {
        float lg = b2[0] + stat[s];
        #pragma unroll
        for (int j = 0; j < HID; j++) lg = fmaf(sh[tid * HID + j], w2[j], lg);
        logits_buf[((size_t)(b * SS + s) * NH + nh) * NW + tid] = lg;
    }
}

// ---------------------------------------------------------------------------
// Kernel 3: TMA double-buffered fuse, CPB=8, streaming stores (validated
// optimum: ~74.5us). DMA prefetch of channel ch+2 overlaps compute/store of
// channel ch; __stcs keeps the 75.5MB write stream from displacing the
// 377MB streaming read in L2.
// ---------------------------------------------------------------------------
#define CPB 8
#define FT  256
#define CH_FLOATS (SS * KK * WW)

__global__ __launch_bounds__(FT) void k_fuse(const float* __restrict__ x,
                                             float* __restrict__ out) {
    const int nh = blockIdx.x;
    const int cb = blockIdx.y;
    const int b  = blockIdx.z;
    const int t  = threadIdx.x;

    extern __shared__ float smem[];
    float* buf = smem;                    // [2][CH_FLOATS]
    float* swt = smem + 2 * CH_FLOATS;    // [SS*NW]
    __shared__ __align__(8) unsigned long long fullbar[2];

    const uint32_t bar0 = smem_u32(&fullbar[0]);
    const uint32_t bar1 = smem_u32(&fullbar[1]);
    const uint32_t bufa = smem_u32(buf);

    const int h0    = nh * KK;
    const int vrows = (HH - h0 < KK) ? (HH - h0) : KK;
    const uint32_t slice_bytes = (uint32_t)vrows * WW * 4;

    if (t == 0) {
        asm volatile("mbarrier.init.shared.b64 [%0], %1;" :: "r"(bar0), "r"(1u));
        asm volatile("mbarrier.init.shared.b64 [%0], %1;" :: "r"(bar1), "r"(1u));
        asm volatile("fence.proxy.async.shared::cta;" ::: "memory");
    }
    if (vrows < KK) {
        const int padrows = KK - vrows;
        const int total = 2 * SS * padrows * WW;
        for (int i = t; i < total; i += FT) {
            const int w  = i % WW;
            const int r  = i / WW;
            const int pr = r % padrows;
            const int ps = r / padrows;
            buf[ps * KK * WW + (vrows + pr) * WW + w] = 0.f;
        }
    }

    auto issue = [&](int ch) {
        const int c = cb * CPB + ch;
        const int p = ch & 1;
        const uint32_t mbar = p ? bar1 : bar0;
        asm volatile("mbarrier.arrive.expect_tx.shared.b64 _, [%0], %1;"
                     :: "r"(mbar), "r"(slice_bytes * SS) : "memory");
        #pragma unroll
        for (int s = 0; s < SS; s++) {
            const float* src = x + ((size_t)((b * SS + s) * CC + c) * HH + h0) * WW;
            const uint32_t dst = bufa + (uint32_t)(p * CH_FLOATS + s * KK * WW) * 4;
            asm volatile(
                "cp.async.bulk.shared::cta.global.mbarrier::complete_tx::bytes "
                "[%0], [%1], %2, [%3];"
                :: "r"(dst), "l"(src), "r"(slice_bytes), "r"(mbar) : "memory");
        }
    };

    if (t == 0) { issue(0); issue(1); }

    if (t < NW) {
        float lg[SS];
        float mx = -1e30f;
        #pragma unroll
        for (int s = 0; s < SS; s++) {
            lg[s] = logits_buf[((size_t)(b * SS + s) * NH + nh) * NW + t];
            mx = fmaxf(mx, lg[s]);
        }
        float sum = 0.f;
        #pragma unroll
        for (int s = 0; s < SS; s++) { lg[s] = expf(lg[s] - mx); sum += lg[s]; }
        const float inv = 1.f / sum;
        #pragma unroll
        for (int s = 0; s < SS; s++) swt[s * NW + t] = lg[s] * inv;
    }
    __syncthreads();

    const int kw   = t / NW;
    const int nw   = t % NW;
    const int wsrc = nw * KK + kw;
    const bool valid = (t < WW) && (wsrc < WW);
    float wts[SS];
    #pragma unroll
    for (int s = 0; s < SS; s++) wts[s] = swt[s * NW + (t % NW)];

    for (int ch = 0; ch < CPB; ch++) {
        const int p  = ch & 1;
        const uint32_t mbar = p ? bar1 : bar0;
        const uint32_t ph = (ch >> 1) & 1;

        asm volatile(
            "{\n\t.reg .pred P;\n\t"
            "WL_%=:\n\t"
            "mbarrier.try_wait.parity.shared.b64 P, [%0], %1;\n\t"
            "@P bra.uni WD_%=;\n\t"
            "bra.uni WL_%=;\n\t"
            "WD_%=:\n\t}"
            :: "r"(mbar), "r"(ph) : "memory");

        if (t < WW) {
            const float* smc = buf + p * CH_FLOATS;
            const int c = cb * CPB + ch;
            float* obase = out + (size_t)(b * CC + c) * HH * WW;
            #pragma unroll
            for (int kh = 0; kh < KK; kh++) {
                const int y = kh * NH + nh;
                if (y < HH) {
                    float vv = 0.f;
                    if (valid) {
                        #pragma unroll
                        for (int s = 0; s < SS; s++)
                            vv = fmaf(wts[s], smc[(s * KK + kh) * WW + wsrc], vv);
                    }
                    __stcs(&obase[(size_t)y * WW + t], vv);   // streaming store
                }
            }
        }
        __syncthreads();
        if (t == 0 && ch + 2 < CPB) issue(ch + 2);
    }
}

// ---------------------------------------------------------------------------
extern "C" void kernel_launch(void* const* d_in, const int* in_sizes, int n_in,
                              void* d_out, int out_size) {
    const float* x    = (const float*)d_in[0];
    const float* w1   = (const float*)d_in[1];
    const float* b1   = (const float*)d_in[2];
    const float* w2   = (const float*)d_in[3];
    const float* b2   = (const float*)d_in[4];
    const float* stat = (const float*)d_in[5];
    float* out = (float*)d_out;

    const int fuse_smem = (2 * CH_FLOATS + SS * NW) * sizeof(float);  // 54320 B
    cudaFuncSetAttribute(k_fuse, cudaFuncAttributeMaxDynamicSharedMemorySize, fuse_smem);

    k_means<<<dim3(CC, BB * SS, 2), MT>>>(x);
    k_mlp  <<<dim3(NH, SS, BB), NW * HID>>>(w1, b1, w2, b2, stat);
    k_fuse <<<dim3(NH, CC / CPB, BB), FT, fuse_smem>>>(x, out);
}

// round 17
// speedup vs baseline: 1.0184x; 1.0065x over previous
#include <cuda_runtime.h>
#include <cstdint>

#define BB 2
#define SS 5
#define CC 256
#define HH 192
#define WW 192
#define KK 7
#define NH 28
#define NW 28
#define HID 16

// g layout: [b][nh][s][c][nw] -> k_mlp block (b,s,nh) reads ONE contiguous
// 28KB chunk (was a 256-way 112B-stride gather). k_means write coalescing
// unchanged (28 contiguous floats per task).
__device__ float g_buf[BB * NH * SS * CC * NW];       // 8.03 MB
__device__ float logits_buf[BB * SS * NH * NW];       // 31.4 KB

__device__ __forceinline__ uint32_t smem_u32(const void* p) {
    uint32_t a;
    asm("{ .reg .u64 t; cvta.to.shared.u64 t, %1; cvt.u32.u64 %0, t; }"
        : "=r"(a) : "l"(p));
    return a;
}

// ---------------------------------------------------------------------------
// Kernel 1: 7x7 window means, DMA-fed depth-2 pipeline (validated optimum).
// Block = half of one (bs,c) image = 14 strips, 7 stages of 2 strips; each
// stage one contiguous 10.75KB cp.async.bulk into depth-2 buffers.
// ---------------------------------------------------------------------------
#define MT     192
#define MROWS  14
#define MSF    (MROWS * WW)

__global__ __launch_bounds__(MT) void k_means(const float* __restrict__ x) {
    const int c  = blockIdx.x;
    const int bs = blockIdx.y;          // b*SS + s
    const int z  = blockIdx.z;          // image half
    const int t  = threadIdx.x;
    const int b  = bs / SS;
    const int sl = bs % SS;             // slice

    __shared__ float buf[2][MSF];                        // 21504 B
    __shared__ float scol[2][2][WW];                     //  3072 B
    __shared__ __align__(8) unsigned long long mbar[2];

    const float* img = x + (size_t)(bs * CC + c) * HH * WW;
    const int strip0 = z * 14;

    auto stage_rows = [&](int s) -> int {
        int rv = HH - (strip0 + s * 2) * KK;
        return rv > MROWS ? MROWS : rv;
    };
    auto issue = [&](int s) {
        const int p = s & 1;
        const uint32_t bytes = (uint32_t)stage_rows(s) * WW * 4;
        const float* src = img + (size_t)(strip0 + s * 2) * KK * WW;
        const uint32_t mb  = smem_u32(&mbar[p]);
        const uint32_t dst = smem_u32(&buf[p][0]);
        asm volatile("mbarrier.arrive.expect_tx.shared.b64 _, [%0], %1;"
                     :: "r"(mb), "r"(bytes) : "memory");
        asm volatile(
            "cp.async.bulk.shared::cta.global.mbarrier::complete_tx::bytes "
            "[%0], [%1], %2, [%3];"
            :: "r"(dst), "l"(src), "r"(bytes), "r"(mb) : "memory");
    };

    if (t == 0) {
        const uint32_t mb0 = smem_u32(&mbar[0]), mb1 = smem_u32(&mbar[1]);
        asm volatile("mbarrier.init.shared.b64 [%0], %1;" :: "r"(mb0), "r"(1u));
        asm volatile("mbarrier.init.shared.b64 [%0], %1;" :: "r"(mb1), "r"(1u));
        asm volatile("fence.proxy.async.shared::cta;" ::: "memory");
        issue(0); issue(1);
    }
    __syncthreads();

    for (int s = 0; s < 7; s++) {
        const int p = s & 1;
        const uint32_t ph = (s >> 1) & 1;
        const uint32_t mb = smem_u32(&mbar[p]);
        asm volatile(
            "{\n\t.reg .pred P;\n\t"
            "WL_%=:\n\t"
            "mbarrier.try_wait.parity.shared.b64 P, [%0], %1;\n\t"
            "@P bra.uni WD_%=;\n\t"
            "bra.uni WL_%=;\n\t"
            "WD_%=:\n\t}"
            :: "r"(mb), "r"(ph) : "memory");

        const int rv = stage_rows(s);
        #pragma unroll
        for (int g = 0; g < 2; g++) {
            float sum = 0.f;
            #pragma unroll
            for (int r = 0; r < KK; r++) {
                const int row = g * KK + r;
                if (row < rv) sum += buf[p][row * WW + t];
            }
            scol[s & 1][g][t] = sum;
        }
        __syncthreads();
        if (t == 0 && s + 2 < 7) issue(s + 2);

        if (t < 2 * NW) {
            const int g = t / NW, nw = t % NW;
            float ws = 0.f;
            #pragma unroll
            for (int i = 0; i < KK; i++) {
                const int w = nw * KK + i;
                if (w < WW) ws += scol[s & 1][g][w];
            }
            const int strip = strip0 + s * 2 + g;
            g_buf[((((size_t)b * NH + strip) * SS + sl) * CC + c) * NW + nw]
                = ws * (1.0f / (KK * KK));
        }
    }
}

// ---------------------------------------------------------------------------
// Kernel 2: tiny MLP over C -> logits. g tile now ONE contiguous 28KB chunk
// -> float4 streaming copy into smem. grid (NH, SS, BB), block 448.
// ---------------------------------------------------------------------------
__global__ void k_mlp(const float* __restrict__ w1, const float* __restrict__ b1,
                      const float* __restrict__ w2, const float* __restrict__ b2,
                      const float* __restrict__ stat) {
    const int nh = blockIdx.x;
    const int s  = blockIdx.y;
    const int b  = blockIdx.z;
    const int tid = threadIdx.x;

    __shared__ float sg[CC * NW];        // [c][nw], matches gmem order
    __shared__ float sw1[HID * CC];
    __shared__ float sh[NW * HID];

    const float4* g4 = (const float4*)(g_buf
        + (((size_t)b * NH + nh) * SS + s) * CC * NW);
    float4* sg4 = (float4*)sg;
    for (int i = tid; i < CC * NW / 4; i += blockDim.x)   // 1792 float4
        sg4[i] = g4[i];
    for (int i = tid; i < HID * CC; i += blockDim.x) sw1[i] = w1[i];
    __syncthreads();

    {
        const int nw = tid % NW;
        const int j  = tid / NW;
        float acc = b1[j];
        #pragma unroll 8
        for (int c = 0; c < CC; c++)
            acc = fmaf(sg[c * NW + nw], sw1[j * CC + c], acc);
        sh[nw * HID + j] = fmaxf(acc, 0.f);
    }
    __syncthreads();

    if (tid < NW) {
        float lg = b2[0] + stat[s];
        #pragma unroll
        for (int j = 0; j < HID; j++) lg = fmaf(sh[tid * HID + j], w2[j], lg);
        logits_buf[((size_t)(b * SS + s) * NH + nh) * NW + tid] = lg;
    }
}

// ---------------------------------------------------------------------------
// Kernel 3: TMA double-buffered fuse, CPB=8, streaming stores (validated
// optimum, unchanged).
// ---------------------------------------------------------------------------
#define CPB 8
#define FT  256
#define CH_FLOATS (SS * KK * WW)

__global__ __launch_bounds__(FT) void k_fuse(const float* __restrict__ x,
                                             float* __restrict__ out) {
    const int nh = blockIdx.x;
    const int cb = blockIdx.y;
    const int b  = blockIdx.z;
    const int t  = threadIdx.x;

    extern __shared__ float smem[];
    float* buf = smem;                    // [2][CH_FLOATS]
    float* swt = smem + 2 * CH_FLOATS;    // [SS*NW]
    __shared__ __align__(8) unsigned long long fullbar[2];

    const uint32_t bar0 = smem_u32(&fullbar[0]);
    const uint32_t bar1 = smem_u32(&fullbar[1]);
    const uint32_t bufa = smem_u32(buf);

    const int h0    = nh * KK;
    const int vrows = (HH - h0 < KK) ? (HH - h0) : KK;
    const uint32_t slice_bytes = (uint32_t)vrows * WW * 4;

    if (t == 0) {
        asm volatile("mbarrier.init.shared.b64 [%0], %1;" :: "r"(bar0), "r"(1u));
        asm volatile("mbarrier.init.shared.b64 [%0], %1;" :: "r"(bar1), "r"(1u));
        asm volatile("fence.proxy.async.shared::cta;" ::: "memory");
    }
    if (vrows < KK) {
        const int padrows = KK - vrows;
        const int total = 2 * SS * padrows * WW;
        for (int i = t; i < total; i += FT) {
            const int w  = i % WW;
            const int r  = i / WW;
            const int pr = r % padrows;
            const int ps = r / padrows;
            buf[ps * KK * WW + (vrows + pr) * WW + w] = 0.f;
        }
    }

    auto issue = [&](int ch) {
        const int c = cb * CPB + ch;
        const int p = ch & 1;
        const uint32_t mbar = p ? bar1 : bar0;
        asm volatile("mbarrier.arrive.expect_tx.shared.b64 _, [%0], %1;"
                     :: "r"(mbar), "r"(slice_bytes * SS) : "memory");
        #pragma unroll
        for (int s = 0; s < SS; s++) {
            const float* src = x + ((size_t)((b * SS + s) * CC + c) * HH + h0) * WW;
            const uint32_t dst = bufa + (uint32_t)(p * CH_FLOATS + s * KK * WW) * 4;
            asm volatile(
                "cp.async.bulk.shared::cta.global.mbarrier::complete_tx::bytes "
                "[%0], [%1], %2, [%3];"
                :: "r"(dst), "l"(src), "r"(slice_bytes), "r"(mbar) : "memory");
        }
    };

    if (t == 0) { issue(0); issue(1); }

    if (t < NW) {
        float lg[SS];
        float mx = -1e30f;
        #pragma unroll
        for (int s = 0; s < SS; s++) {
            lg[s] = logits_buf[((size_t)(b * SS + s) * NH + nh) * NW + t];
            mx = fmaxf(mx, lg[s]);
        }
        float sum = 0.f;
        #pragma unroll
        for (int s = 0; s < SS; s++) { lg[s] = expf(lg[s] - mx); sum += lg[s]; }
        const float inv = 1.f / sum;
        #pragma unroll
        for (int s = 0; s < SS; s++) swt[s * NW + t] = lg[s] * inv;
    }
    __syncthreads();

    const int kw   = t / NW;
    const int nw   = t % NW;
    const int wsrc = nw * KK + kw;
    const bool valid = (t < WW) && (wsrc < WW);
    float wts[SS];
    #pragma unroll
    for (int s = 0; s < SS; s++) wts[s] = swt[s * NW + (t % NW)];

    for (int ch = 0; ch < CPB; ch++) {
        const int p  = ch & 1;
        const uint32_t mbar = p ? bar1 : bar0;
        const uint32_t ph = (ch >> 1) & 1;

        asm volatile(
            "{\n\t.reg .pred P;\n\t"
            "WL_%=:\n\t"
            "mbarrier.try_wait.parity.shared.b64 P, [%0], %1;\n\t"
            "@P bra.uni WD_%=;\n\t"
            "bra.uni WL_%=;\n\t"
            "WD_%=:\n\t}"
            :: "r"(mbar), "r"(ph) : "memory");

        if (t < WW) {
            const float* smc = buf + p * CH_FLOATS;
            const int c = cb * CPB + ch;
            float* obase = out + (size_t)(b * CC + c) * HH * WW;
            #pragma unroll
            for (int kh = 0; kh < KK; kh++) {
                const int y = kh * NH + nh;
                if (y < HH) {
                    float vv = 0.f;
                    if (valid) {
                        #pragma unroll
                        for (int s = 0; s < SS; s++)
                            vv = fmaf(wts[s], smc[(s * KK + kh) * WW + wsrc], vv);
                    }
                    __stcs(&obase[(size_t)y * WW + t], vv);   // streaming store
                }
            }
        }
        __syncthreads();
        if (t == 0 && ch + 2 < CPB) issue(ch + 2);
    }
}

// ---------------------------------------------------------------------------
extern "C" void kernel_launch(void* const* d_in, const int* in_sizes, int n_in,
                              void* d_out, int out_size) {
    const float* x    = (const float*)d_in[0];
    const float* w1   = (const float*)d_in[1];
    const float* b1   = (const float*)d_in[2];
    const float* w2   = (const float*)d_in[3];
    const float* b2   = (const float*)d_in[4];
    const float* stat = (const float*)d_in[5];
    float* out = (float*)d_out;

    const int fuse_smem = (2 * CH_FLOATS + SS * NW) * sizeof(float);  // 54320 B
    cudaFuncSetAttribute(k_fuse, cudaFuncAttributeMaxDynamicSharedMemorySize, fuse_smem);

    k_means<<<dim3(CC, BB * SS, 2), MT>>>(x);
    k_mlp  <<<dim3(NH, SS, BB), NW * HID>>>(w1, b1, w2, b2, stat);
    k_fuse <<<dim3(NH, CC / CPB, BB), FT, fuse_smem>>>(x, out);
}